// round 13
// baseline (speedup 1.0000x reference)
#include <cuda_runtime.h>
#include <cstdint>
#include <stdint.h>
#include <math.h>

#define B_    64
#define T_    50000
#define D_    160
#define PATCH 25
#define L_    2000
#define KENV  25
#define KBUR  9
#define KPRE  9

#define TILE  500
#define NTHR1 128

// residue-array strides (u64 units), padded to scatter banks
#define SXN   137
#define SDXN  133
#define SS0N  129

// ---- stage2 config ----
#define S2T     512
#define NR2     128
#define NT2     1000
#define AROW    100
#define S2GRID  148
#define S2ABUF  (NR2*AROW)
#define S2_SMEM_BYTES (16000*4 + 2*S2ABUF*4)

typedef unsigned long long u64;
typedef unsigned int u32;

__device__ float4 g_xs[(size_t)B_ * T_];

__device__ __forceinline__ u64 f2fma(u64 a, u64 b, u64 c) {
    u64 d; asm("fma.rn.f32x2 %0,%1,%2,%3;" : "=l"(d) : "l"(a), "l"(b), "l"(c)); return d;
}
__device__ __forceinline__ u64 f2add(u64 a, u64 b) {
    u64 d; asm("add.rn.f32x2 %0,%1,%2;" : "=l"(d) : "l"(a), "l"(b)); return d;
}
__device__ __forceinline__ u64 dup2(float x) {
    u64 r; asm("mov.b64 %0,{%1,%1};" : "=l"(r) : "f"(x)); return r;
}
__device__ __forceinline__ u64 pack2(float a, float b) {
    u64 r; asm("mov.b64 %0,{%1,%2};" : "=l"(r) : "f"(a), "f"(b)); return r;
}
__device__ __forceinline__ void unpack2(u64 v, float& lo, float& hi) {
    asm("mov.b64 {%0,%1},%2;" : "=f"(lo), "=f"(hi) : "l"(v));
}
__device__ __forceinline__ float softplusf_(float v) {
    return fmaxf(v, 0.0f) + log1pf(expf(-fabsf(v)));
}

// Branch-free exact-GELU: Phi via A&S 7.1.26 erf (abs err <= 1.5e-7).
__device__ __forceinline__ float gelu_fast(float x) {
    float z  = x * 0.70710678118654752f;
    float az = fabsf(z);
    float t  = __fdividef(1.0f, fmaf(0.3275911f, az, 1.0f));
    float p  = t * fmaf(t, fmaf(t, fmaf(t, fmaf(t, 1.061405429f, -1.453152027f),
                                        1.421413741f), -0.284496736f), 0.254829592f);
    float e  = __expf(-az * az);
    float erf_az = fmaf(-p, e, 1.0f);
    float erf_z  = copysignf(erf_az, z);
    return 0.5f * x * (1.0f + erf_z);
}

__device__ __forceinline__ void cpasync16(u32 dst, const void* src) {
    asm volatile("cp.async.cg.shared.global [%0], [%1], 16;" :: "r"(dst), "l"(src));
}
#define CP_COMMIT() asm volatile("cp.async.commit_group;")
#define CP_WAIT1()  asm volatile("cp.async.wait_group 1;")

// ---------------------------------------------------------------------------
// Stage 1: fused front pipeline (unchanged from R12 winner).
// ---------------------------------------------------------------------------
__global__ __launch_bounds__(NTHR1) void stage1_kernel(
    const float4* __restrict__ X, const float4* __restrict__ M,
    const float*  __restrict__ w_env, const float* __restrict__ w_burst,
    const float*  __restrict__ synergy_raw, const float* __restrict__ w_pre_dw,
    const float*  __restrict__ w_pre_pw, float* __restrict__ out_mpatch)
{
    __shared__ u64 sx_r  [2][4][SXN];
    __shared__ u64 sabs_r[2][4][SXN];
    __shared__ u64 sdx_r [2][4][SDXN];
    __shared__ u64 sS0_r [2][4][SS0N];
    __shared__ unsigned smask_r[4][126];
    __shared__ float smt[TILE];
    __shared__ u64 swe_p[2][KENV], swb_p[2][KBUR], swd_p[2][KPRE];
    __shared__ float4 slut[16];
    __shared__ float  slmt[16];

    const int tid  = threadIdx.x;
    const int tile = blockIdx.x;
    const int b    = blockIdx.y;
    const int t0   = tile * TILE;

    float Wm[4][4];
    #pragma unroll
    for (int m = 0; m < 4; m++) {
        float r0 = softplusf_(synergy_raw[m*4+0]);
        float r1 = softplusf_(synergy_raw[m*4+1]);
        float r2 = softplusf_(synergy_raw[m*4+2]);
        float r3 = softplusf_(synergy_raw[m*4+3]);
        float inv = 1.0f / fmaxf(r0+r1+r2+r3, 1e-6f);
        Wm[m][0]=r0*inv; Wm[m][1]=r1*inv; Wm[m][2]=r2*inv; Wm[m][3]=r3*inv;
    }
    u64 Wp01[4], Wp23[4], pw01[4], pw23[4];
    #pragma unroll
    for (int c = 0; c < 4; c++) {
        Wp01[c] = pack2(Wm[0][c], Wm[1][c]);
        Wp23[c] = pack2(Wm[2][c], Wm[3][c]);
        pw01[c] = pack2(w_pre_pw[0*4+c], w_pre_pw[1*4+c]);
        pw23[c] = pack2(w_pre_pw[2*4+c], w_pre_pw[3*4+c]);
    }

    if (tid < KENV) {
        swe_p[0][tid] = pack2(0.9f*w_env[tid],    0.9f*w_env[25+tid]);
        swe_p[1][tid] = pack2(0.9f*w_env[50+tid], 0.9f*w_env[75+tid]);
    }
    if (tid < KBUR) {
        swb_p[0][tid] = pack2(0.6f*w_burst[tid],    0.6f*w_burst[9+tid]);
        swb_p[1][tid] = pack2(0.6f*w_burst[18+tid], 0.6f*w_burst[27+tid]);
        swd_p[0][tid] = pack2(w_pre_dw[tid],    w_pre_dw[9+tid]);
        swd_p[1][tid] = pack2(w_pre_dw[18+tid], w_pre_dw[27+tid]);
    }
    if (tid < 16) {
        float mm[4]; float4 sv;
        #pragma unroll
        for (int c = 0; c < 4; c++) mm[c] = (float)((tid >> c) & 1);
        float v0 = Wm[0][0]*mm[0]+Wm[0][1]*mm[1]+Wm[0][2]*mm[2]+Wm[0][3]*mm[3];
        float v1 = Wm[1][0]*mm[0]+Wm[1][1]*mm[1]+Wm[1][2]*mm[2]+Wm[1][3]*mm[3];
        float v2 = Wm[2][0]*mm[0]+Wm[2][1]*mm[1]+Wm[2][2]*mm[2]+Wm[2][3]*mm[3];
        float v3 = Wm[3][0]*mm[0]+Wm[3][1]*mm[1]+Wm[3][2]*mm[2]+Wm[3][3]*mm[3];
        sv.x = fminf(fmaxf(v0,0.f),1.f); sv.y = fminf(fmaxf(v1,0.f),1.f);
        sv.z = fminf(fmaxf(v2,0.f),1.f); sv.w = fminf(fmaxf(v3,0.f),1.f);
        slut[tid] = sv;
        slmt[tid] = ((sv.x+sv.y+sv.z+sv.w) > 0.f) ? 1.f : 0.f;
    }

    // Phase A: x = X*M, |x|, mask bits -> residue arrays
    const float4* Xb = X + (size_t)b * T_;
    const float4* Mb = M + (size_t)b * T_;
    for (int j = tid; j < TILE + 32; j += NTHR1) {
        int t = t0 - 16 + j;
        u64 x01 = 0, x23 = 0, a01 = 0, a23 = 0;
        if (t >= 0 && t < T_) {
            float4 X4 = Xb[t], M4 = Mb[t];
            float xx = X4.x*M4.x, xy = X4.y*M4.y, xz = X4.z*M4.z, xw = X4.w*M4.w;
            x01 = pack2(xx, xy); x23 = pack2(xz, xw);
            a01 = pack2(fabsf(xx), fabsf(xy)); a23 = pack2(fabsf(xz), fabsf(xw));
            if (j >= 16 && j < 16 + TILE) {
                unsigned mk = (M4.x > 0.f ? 1u : 0u) | (M4.y > 0.f ? 2u : 0u)
                            | (M4.z > 0.f ? 4u : 0u) | (M4.w > 0.f ? 8u : 0u);
                smask_r[(j-16)&3][(j-16)>>2] = mk;
            }
        }
        int jr = j & 3, jq = j >> 2;
        sx_r[0][jr][jq] = x01;  sx_r[1][jr][jq] = x23;
        sabs_r[0][jr][jq] = a01; sabs_r[1][jr][jq] = a23;
    }
    __syncthreads();

    // Phase dx: |x[t]-x[t-1]|
    for (int i = tid; i < TILE + 16; i += NTHR1) {
        int t = t0 - 8 + i;
        u64 r01 = 0, r23 = 0;
        if (t >= 1 && t < T_) {
            int ja = i + 8, jc = i + 7;
            u64 a01 = sx_r[0][ja&3][ja>>2], a23 = sx_r[1][ja&3][ja>>2];
            u64 c01 = sx_r[0][jc&3][jc>>2], c23 = sx_r[1][jc&3][jc>>2];
            float ax, ay, az, aw, cx, cy, cz, cw;
            unpack2(a01, ax, ay); unpack2(a23, az, aw);
            unpack2(c01, cx, cy); unpack2(c23, cz, cw);
            r01 = pack2(fabsf(ax-cx), fabsf(ay-cy));
            r23 = pack2(fabsf(az-cz), fabsf(aw-cw));
        }
        sdx_r[0][i&3][i>>2] = r01; sdx_r[1][i&3][i>>2] = r23;
    }
    __syncthreads();

    const u64 c02 = pack2(0.2f, 0.2f);

    // Phase B: env(25) + burst(9) + 0.2x, synergy mix -> sS0. 4 pts/thread.
    if (tid < 127) {
        u64 xm[2][4];
        #pragma unroll
        for (int pp = 0; pp < 2; pp++) {
            u64 e0=0,e1=0,e2=0,e3=0;
            u64 d0 = sabs_r[pp][0][tid];
            u64 d1 = sabs_r[pp][1][tid];
            u64 d2 = sabs_r[pp][2][tid];
            #pragma unroll
            for (int k = 0; k < KENV; k++) {
                u64 w  = swe_p[pp][k];
                u64 d3 = sabs_r[pp][(k+3)&3][tid + ((k+3)>>2)];
                e0 = f2fma(d0,w,e0); e1 = f2fma(d1,w,e1);
                e2 = f2fma(d2,w,e2); e3 = f2fma(d3,w,e3);
                d0 = d1; d1 = d2; d2 = d3;
            }
            u64 u0=0,u1=0,u2=0,u3=0;
            d0 = sdx_r[pp][0][tid];
            d1 = sdx_r[pp][1][tid];
            d2 = sdx_r[pp][2][tid];
            #pragma unroll
            for (int k = 0; k < KBUR; k++) {
                u64 w  = swb_p[pp][k];
                u64 d3 = sdx_r[pp][(k+3)&3][tid + ((k+3)>>2)];
                u0 = f2fma(d0,w,u0); u1 = f2fma(d1,w,u1);
                u2 = f2fma(d2,w,u2); u3 = f2fma(d3,w,u3);
                d0 = d1; d1 = d2; d2 = d3;
            }
            xm[pp][0] = f2fma(sx_r[pp][0][tid+3], c02, f2add(e0,u0));
            xm[pp][1] = f2fma(sx_r[pp][1][tid+3], c02, f2add(e1,u1));
            xm[pp][2] = f2fma(sx_r[pp][2][tid+3], c02, f2add(e2,u2));
            xm[pp][3] = f2fma(sx_r[pp][3][tid+3], c02, f2add(e3,u3));
        }
        #pragma unroll
        for (int r = 0; r < 4; r++) {
            float m0,m1,m2,m3;
            unpack2(xm[0][r], m0, m1); unpack2(xm[1][r], m2, m3);
            u64 dd0 = dup2(m0), dd1 = dup2(m1), dd2 = dup2(m2), dd3 = dup2(m3);
            u64 s01 = 0ull, s23 = 0ull;
            s01 = f2fma(dd0, Wp01[0], s01); s01 = f2fma(dd1, Wp01[1], s01);
            s01 = f2fma(dd2, Wp01[2], s01); s01 = f2fma(dd3, Wp01[3], s01);
            s23 = f2fma(dd0, Wp23[0], s23); s23 = f2fma(dd1, Wp23[1], s23);
            s23 = f2fma(dd2, Wp23[2], s23); s23 = f2fma(dd3, Wp23[3], s23);
            int tb = t0 - 4 + 4*tid + r;
            if (tb < 0 || tb >= T_) { s01 = 0ull; s23 = 0ull; }
            sS0_r[0][r][tid] = s01;
            sS0_r[1][r][tid] = s23;
        }
    }
    __syncthreads();

    // Phase C: dwconv K=9 + gelu, pointwise + gelu, mask, xs, m_time. 4 pts/thread.
    if (tid < 125) {
        const int i0 = 4 * tid;
        u64 aa[2][4];
        #pragma unroll
        for (int pp = 0; pp < 2; pp++) {
            u64 a0=0,a1=0,a2=0,a3=0;
            u64 d0 = sS0_r[pp][0][tid];
            u64 d1 = sS0_r[pp][1][tid];
            u64 d2 = sS0_r[pp][2][tid];
            #pragma unroll
            for (int k = 0; k < KPRE; k++) {
                u64 w  = swd_p[pp][k];
                u64 d3 = sS0_r[pp][(k+3)&3][tid + ((k+3)>>2)];
                a0 = f2fma(d0,w,a0); a1 = f2fma(d1,w,a1);
                a2 = f2fma(d2,w,a2); a3 = f2fma(d3,w,a3);
                d0 = d1; d1 = d2; d2 = d3;
            }
            aa[pp][0]=a0; aa[pp][1]=a1; aa[pp][2]=a2; aa[pp][3]=a3;
        }
        #pragma unroll
        for (int r = 0; r < 4; r++) {
            float g0,g1,g2,g3;
            unpack2(aa[0][r], g0, g1); unpack2(aa[1][r], g2, g3);
            float s1_0 = gelu_fast(g0), s1_1 = gelu_fast(g1);
            float s1_2 = gelu_fast(g2), s1_3 = gelu_fast(g3);

            u64 t01 = 0ull, t23 = 0ull;
            u64 e0 = dup2(s1_0), e1 = dup2(s1_1), e2 = dup2(s1_2), e3 = dup2(s1_3);
            t01 = f2fma(e0, pw01[0], t01); t01 = f2fma(e1, pw01[1], t01);
            t01 = f2fma(e2, pw01[2], t01); t01 = f2fma(e3, pw01[3], t01);
            t23 = f2fma(e0, pw23[0], t23); t23 = f2fma(e1, pw23[1], t23);
            t23 = f2fma(e2, pw23[2], t23); t23 = f2fma(e3, pw23[3], t23);
            float v0,v1,v2,v3;
            unpack2(t01, v0, v1); unpack2(t23, v2, v3);

            unsigned mk = smask_r[r][tid];
            float4 smv = slut[mk];
            float4 xs;
            xs.x = gelu_fast(v0) * smv.x;
            xs.y = gelu_fast(v1) * smv.y;
            xs.z = gelu_fast(v2) * smv.z;
            xs.w = gelu_fast(v3) * smv.w;
            g_xs[(size_t)b * T_ + t0 + i0 + r] = xs;
            smt[i0 + r] = slmt[mk];
        }
    }
    __syncthreads();

    // m_patch: 20 patches per tile
    if (tid < TILE / PATCH) {
        float s = 0.f;
        int base = tid * PATCH;
        #pragma unroll
        for (int p = 0; p < PATCH; p++) s += smt[base + p];
        out_mpatch[b * L_ + tile * (TILE/PATCH) + tid] =
            (s * (1.0f/25.0f) > 0.1f) ? 1.0f : 0.0f;
    }
}

// ---------------------------------------------------------------------------
// Stage 2: [128000x100]x[100x160] + LayerNorm.
// LDS.128 both streams: W float4 [kk2=25][160], A broadcast ulonglong2.
// ---------------------------------------------------------------------------
__global__ __launch_bounds__(S2T, 1) void stage2_kernel(
    const float* __restrict__ w_proj, const float* __restrict__ ln_gamma,
    const float* __restrict__ ln_beta, float* __restrict__ out_h)
{
    extern __shared__ float sm2[];
    float* sW = sm2;               // float4 [kk2][d]: k = 4*kk2 + e
    float* sA = sm2 + 16000;       // 2 buffers of [128][100]

    const int tid = threadIdx.x;
    const int tx  = tid & 31;
    const int ty  = tid >> 5;

    // W into smem: sW4[kk2*160 + d] = (W[k0][d], W[k0+1][d], W[k0+2][d], W[k0+3][d])
    // A float index k = 4p+m  ->  w_proj[d*100 + (k&3)*25 + (k>>2)]
    for (int i = tid; i < 4000; i += S2T) {
        int kk2 = i / 160, d = i - kk2*160;
        float4 w;
        int k0 = 4*kk2;
        w.x = w_proj[d*100 + ((k0+0) & 3)*25 + ((k0+0) >> 2)];
        w.y = w_proj[d*100 + ((k0+1) & 3)*25 + ((k0+1) >> 2)];
        w.z = w_proj[d*100 + ((k0+2) & 3)*25 + ((k0+2) >> 2)];
        w.w = w_proj[d*100 + ((k0+3) & 3)*25 + ((k0+3) >> 2)];
        *(float4*)&sW[4*i] = w;
    }
    float gam[5], bet[5];
    #pragma unroll
    for (int c = 0; c < 5; c++) { gam[c] = ln_gamma[tx + 32*c]; bet[c] = ln_beta[tx + 32*c]; }

    const float4* gxs = (const float4*)g_xs;
    u32 sA_u32;
    { void* p = sA; asm("{ .reg .u64 t; cvta.to.shared.u64 t, %1; cvt.u32.u64 %0, t; }"
                        : "=r"(sA_u32) : "l"(p)); }

    {
        int base = blockIdx.x * (NR2*25);
        #pragma unroll
        for (int it = 0; it < 7; it++) {
            int i = tid + it * S2T;
            if (i < NR2*25) {
                int r = i / 25, p = i - r*25;
                cpasync16(sA_u32 + (r*AROW + 4*p)*4, gxs + base + i);
            }
        }
        CP_COMMIT();
    }

    int cur = 0;
    for (int tt = blockIdx.x; tt < NT2; tt += S2GRID) {
        int nt = tt + S2GRID;
        if (nt < NT2) {
            int base = nt * (NR2*25);
            u32 dst = sA_u32 + (u32)(cur^1) * (S2ABUF*4);
            #pragma unroll
            for (int it = 0; it < 7; it++) {
                int i = tid + it * S2T;
                if (i < NR2*25) {
                    int r = i / 25, p = i - r*25;
                    cpasync16(dst + (r*AROW + 4*p)*4, gxs + base + i);
                }
            }
        }
        CP_COMMIT();
        CP_WAIT1();
        __syncthreads();

        u64 acc[8][5];
        #pragma unroll
        for (int r = 0; r < 8; r++)
            #pragma unroll
            for (int c = 0; c < 5; c++) acc[r][c] = 0ull;

        // A rows of this warp, viewed as ulonglong2 (16B) chunks: row r, chunk kk2
        const ulonglong2* aT2 = (const ulonglong2*)(sA + cur * S2ABUF + (ty*8) * AROW);
        const ulonglong2* wp2 = (const ulonglong2*)sW;

        #pragma unroll 5
        for (int kk2 = 0; kk2 < 25; kk2++) {
            ulonglong2 wv[5];
            #pragma unroll
            for (int c = 0; c < 5; c++) wv[c] = wp2[kk2*160 + tx + 32*c];
            #pragma unroll
            for (int r = 0; r < 8; r++) {
                ulonglong2 av = aT2[r*25 + kk2];
                #pragma unroll
                for (int c = 0; c < 5; c++) {
                    acc[r][c] = f2fma(av.x, wv[c].x, acc[r][c]);
                    acc[r][c] = f2fma(av.y, wv[c].y, acc[r][c]);
                }
            }
        }

        #pragma unroll
        for (int r = 0; r < 8; r++) {
            float h[5]; float s = 0.f, q = 0.f;
            #pragma unroll
            for (int c = 0; c < 5; c++) {
                float lo, hi; unpack2(acc[r][c], lo, hi);
                h[c] = lo + hi;
                s += h[c]; q += h[c]*h[c];
            }
            #pragma unroll
            for (int off = 16; off > 0; off >>= 1) {
                s += __shfl_xor_sync(0xffffffffu, s, off);
                q += __shfl_xor_sync(0xffffffffu, q, off);
            }
            float mu = s * (1.0f/160.0f);
            float rs = rsqrtf(q * (1.0f/160.0f) - mu*mu + 1e-5f);
            int rg = tt*NR2 + ty*8 + r;
            float* o = out_h + (size_t)rg * D_ + tx;
            #pragma unroll
            for (int c = 0; c < 5; c++)
                o[32*c] = (h[c] - mu) * rs * gam[c] + bet[c];
        }
        __syncthreads();
        cur ^= 1;
    }
}

// ---------------------------------------------------------------------------
extern "C" void kernel_launch(void* const* d_in, const int* in_sizes, int n_in,
                              void* d_out, int out_size) {
    const float* X           = (const float*)d_in[0];
    const float* M           = (const float*)d_in[1];
    const float* w_env       = (const float*)d_in[2];
    const float* w_burst     = (const float*)d_in[3];
    const float* synergy_raw = (const float*)d_in[4];
    const float* w_pre_dw    = (const float*)d_in[5];
    const float* w_pre_pw    = (const float*)d_in[6];
    const float* w_proj      = (const float*)d_in[7];
    const float* ln_gamma    = (const float*)d_in[8];
    const float* ln_beta     = (const float*)d_in[9];

    float* out_h  = (float*)d_out;
    float* out_mp = out_h + (size_t)B_ * L_ * D_;

    cudaFuncSetAttribute(stage2_kernel,
                         cudaFuncAttributeMaxDynamicSharedMemorySize,
                         S2_SMEM_BYTES);

    dim3 g1(T_ / TILE, B_);
    stage1_kernel<<<g1, NTHR1>>>((const float4*)X, (const float4*)M,
                                 w_env, w_burst, synergy_raw,
                                 w_pre_dw, w_pre_pw, out_mp);
    stage2_kernel<<<S2GRID, S2T, S2_SMEM_BYTES>>>(w_proj, ln_gamma, ln_beta, out_h);
}

// round 14
// speedup vs baseline: 1.0878x; 1.0878x over previous
#include <cuda_runtime.h>
#include <cstdint>
#include <stdint.h>
#include <math.h>

#define B_    64
#define T_    50000
#define D_    160
#define PATCH 25
#define L_    2000
#define KENV  25
#define KBUR  9
#define KPRE  9

#define TILE  500
#define NTHR1 128

// residue-array strides (u64 units), padded to scatter banks
#define SXN   137
#define SDXN  133
#define SS0N  129

// ---- stage2 config ----
#define S2T     512
#define NR2     128
#define NT2     1000
#define AROW    100
#define S2GRID  148
#define S2ABUF  (NR2*AROW)
#define S2_SMEM_BYTES (16000*4 + 2*S2ABUF*4)

typedef unsigned long long u64;
typedef unsigned int u32;

__device__ float4 g_xs[(size_t)B_ * T_];

__device__ __forceinline__ u64 f2fma(u64 a, u64 b, u64 c) {
    u64 d; asm("fma.rn.f32x2 %0,%1,%2,%3;" : "=l"(d) : "l"(a), "l"(b), "l"(c)); return d;
}
__device__ __forceinline__ u64 f2add(u64 a, u64 b) {
    u64 d; asm("add.rn.f32x2 %0,%1,%2;" : "=l"(d) : "l"(a), "l"(b)); return d;
}
__device__ __forceinline__ u64 dup2(float x) {
    u64 r; asm("mov.b64 %0,{%1,%1};" : "=l"(r) : "f"(x)); return r;
}
__device__ __forceinline__ u64 pack2(float a, float b) {
    u64 r; asm("mov.b64 %0,{%1,%2};" : "=l"(r) : "f"(a), "f"(b)); return r;
}
__device__ __forceinline__ void unpack2(u64 v, float& lo, float& hi) {
    asm("mov.b64 {%0,%1},%2;" : "=f"(lo), "=f"(hi) : "l"(v));
}
__device__ __forceinline__ float softplusf_(float v) {
    return fmaxf(v, 0.0f) + log1pf(expf(-fabsf(v)));
}

// Branch-free exact-GELU: Phi via A&S 7.1.26 erf (abs err <= 1.5e-7).
__device__ __forceinline__ float gelu_fast(float x) {
    float z  = x * 0.70710678118654752f;
    float az = fabsf(z);
    float t  = __fdividef(1.0f, fmaf(0.3275911f, az, 1.0f));
    float p  = t * fmaf(t, fmaf(t, fmaf(t, fmaf(t, 1.061405429f, -1.453152027f),
                                        1.421413741f), -0.284496736f), 0.254829592f);
    float e  = __expf(-az * az);
    float erf_az = fmaf(-p, e, 1.0f);
    float erf_z  = copysignf(erf_az, z);
    return 0.5f * x * (1.0f + erf_z);
}

__device__ __forceinline__ void cpasync16(u32 dst, const void* src) {
    asm volatile("cp.async.cg.shared.global [%0], [%1], 16;" :: "r"(dst), "l"(src));
}
#define CP_COMMIT() asm volatile("cp.async.commit_group;")
#define CP_WAIT1()  asm volatile("cp.async.wait_group 1;")

// ---------------------------------------------------------------------------
// Stage 1: fused front pipeline. Softplus setup hoisted: 16 threads compute
// softplus once into smem; all threads build Wm cheaply from it.
// ---------------------------------------------------------------------------
__global__ __launch_bounds__(NTHR1) void stage1_kernel(
    const float4* __restrict__ X, const float4* __restrict__ M,
    const float*  __restrict__ w_env, const float* __restrict__ w_burst,
    const float*  __restrict__ synergy_raw, const float* __restrict__ w_pre_dw,
    const float*  __restrict__ w_pre_pw, float* __restrict__ out_mpatch)
{
    __shared__ u64 sx_r  [2][4][SXN];
    __shared__ u64 sabs_r[2][4][SXN];
    __shared__ u64 sdx_r [2][4][SDXN];
    __shared__ u64 sS0_r [2][4][SS0N];
    __shared__ unsigned smask_r[4][126];
    __shared__ float smt[TILE];
    __shared__ u64 swe_p[2][KENV], swb_p[2][KBUR], swd_p[2][KPRE];
    __shared__ float4 slut[16];
    __shared__ float  slmt[16];
    __shared__ float  ssp[16];

    const int tid  = threadIdx.x;
    const int tile = blockIdx.x;
    const int b    = blockIdx.y;
    const int t0   = tile * TILE;

    // ---- cheap setup: softplus once per block ----
    if (tid < 16) ssp[tid] = softplusf_(synergy_raw[tid]);
    if (tid < KENV) {
        swe_p[0][tid] = pack2(0.9f*w_env[tid],    0.9f*w_env[25+tid]);
        swe_p[1][tid] = pack2(0.9f*w_env[50+tid], 0.9f*w_env[75+tid]);
    }
    if (tid < KBUR) {
        swb_p[0][tid] = pack2(0.6f*w_burst[tid],    0.6f*w_burst[9+tid]);
        swb_p[1][tid] = pack2(0.6f*w_burst[18+tid], 0.6f*w_burst[27+tid]);
        swd_p[0][tid] = pack2(w_pre_dw[tid],    w_pre_dw[9+tid]);
        swd_p[1][tid] = pack2(w_pre_dw[18+tid], w_pre_dw[27+tid]);
    }
    __syncthreads();

    float Wm[4][4];
    #pragma unroll
    for (int m = 0; m < 4; m++) {
        float r0 = ssp[m*4+0], r1 = ssp[m*4+1], r2 = ssp[m*4+2], r3 = ssp[m*4+3];
        float inv = __fdividef(1.0f, fmaxf(r0+r1+r2+r3, 1e-6f));
        Wm[m][0]=r0*inv; Wm[m][1]=r1*inv; Wm[m][2]=r2*inv; Wm[m][3]=r3*inv;
    }
    u64 Wp01[4], Wp23[4], pw01[4], pw23[4];
    #pragma unroll
    for (int c = 0; c < 4; c++) {
        Wp01[c] = pack2(Wm[0][c], Wm[1][c]);
        Wp23[c] = pack2(Wm[2][c], Wm[3][c]);
        pw01[c] = pack2(w_pre_pw[0*4+c], w_pre_pw[1*4+c]);
        pw23[c] = pack2(w_pre_pw[2*4+c], w_pre_pw[3*4+c]);
    }

    if (tid < 16) {
        float mm[4]; float4 sv;
        #pragma unroll
        for (int c = 0; c < 4; c++) mm[c] = (float)((tid >> c) & 1);
        float v0 = Wm[0][0]*mm[0]+Wm[0][1]*mm[1]+Wm[0][2]*mm[2]+Wm[0][3]*mm[3];
        float v1 = Wm[1][0]*mm[0]+Wm[1][1]*mm[1]+Wm[1][2]*mm[2]+Wm[1][3]*mm[3];
        float v2 = Wm[2][0]*mm[0]+Wm[2][1]*mm[1]+Wm[2][2]*mm[2]+Wm[2][3]*mm[3];
        float v3 = Wm[3][0]*mm[0]+Wm[3][1]*mm[1]+Wm[3][2]*mm[2]+Wm[3][3]*mm[3];
        sv.x = fminf(fmaxf(v0,0.f),1.f); sv.y = fminf(fmaxf(v1,0.f),1.f);
        sv.z = fminf(fmaxf(v2,0.f),1.f); sv.w = fminf(fmaxf(v3,0.f),1.f);
        slut[tid] = sv;
        slmt[tid] = ((sv.x+sv.y+sv.z+sv.w) > 0.f) ? 1.f : 0.f;
    }

    // Phase A: x = X*M, |x|, mask bits -> residue arrays
    const float4* Xb = X + (size_t)b * T_;
    const float4* Mb = M + (size_t)b * T_;
    for (int j = tid; j < TILE + 32; j += NTHR1) {
        int t = t0 - 16 + j;
        u64 x01 = 0, x23 = 0, a01 = 0, a23 = 0;
        if (t >= 0 && t < T_) {
            float4 X4 = Xb[t], M4 = Mb[t];
            float xx = X4.x*M4.x, xy = X4.y*M4.y, xz = X4.z*M4.z, xw = X4.w*M4.w;
            x01 = pack2(xx, xy); x23 = pack2(xz, xw);
            a01 = pack2(fabsf(xx), fabsf(xy)); a23 = pack2(fabsf(xz), fabsf(xw));
            if (j >= 16 && j < 16 + TILE) {
                unsigned mk = (M4.x > 0.f ? 1u : 0u) | (M4.y > 0.f ? 2u : 0u)
                            | (M4.z > 0.f ? 4u : 0u) | (M4.w > 0.f ? 8u : 0u);
                smask_r[(j-16)&3][(j-16)>>2] = mk;
            }
        }
        int jr = j & 3, jq = j >> 2;
        sx_r[0][jr][jq] = x01;  sx_r[1][jr][jq] = x23;
        sabs_r[0][jr][jq] = a01; sabs_r[1][jr][jq] = a23;
    }
    __syncthreads();

    // Phase dx: |x[t]-x[t-1]|
    for (int i = tid; i < TILE + 16; i += NTHR1) {
        int t = t0 - 8 + i;
        u64 r01 = 0, r23 = 0;
        if (t >= 1 && t < T_) {
            int ja = i + 8, jc = i + 7;
            u64 a01 = sx_r[0][ja&3][ja>>2], a23 = sx_r[1][ja&3][ja>>2];
            u64 c01 = sx_r[0][jc&3][jc>>2], c23 = sx_r[1][jc&3][jc>>2];
            float ax, ay, az, aw, cx, cy, cz, cw;
            unpack2(a01, ax, ay); unpack2(a23, az, aw);
            unpack2(c01, cx, cy); unpack2(c23, cz, cw);
            r01 = pack2(fabsf(ax-cx), fabsf(ay-cy));
            r23 = pack2(fabsf(az-cz), fabsf(aw-cw));
        }
        sdx_r[0][i&3][i>>2] = r01; sdx_r[1][i&3][i>>2] = r23;
    }
    __syncthreads();

    const u64 c02 = pack2(0.2f, 0.2f);

    // Phase B: env(25) + burst(9) + 0.2x, synergy mix -> sS0. 4 pts/thread.
    if (tid < 127) {
        u64 xm[2][4];
        #pragma unroll
        for (int pp = 0; pp < 2; pp++) {
            u64 e0=0,e1=0,e2=0,e3=0;
            u64 d0 = sabs_r[pp][0][tid];
            u64 d1 = sabs_r[pp][1][tid];
            u64 d2 = sabs_r[pp][2][tid];
            #pragma unroll
            for (int k = 0; k < KENV; k++) {
                u64 w  = swe_p[pp][k];
                u64 d3 = sabs_r[pp][(k+3)&3][tid + ((k+3)>>2)];
                e0 = f2fma(d0,w,e0); e1 = f2fma(d1,w,e1);
                e2 = f2fma(d2,w,e2); e3 = f2fma(d3,w,e3);
                d0 = d1; d1 = d2; d2 = d3;
            }
            u64 u0=0,u1=0,u2=0,u3=0;
            d0 = sdx_r[pp][0][tid];
            d1 = sdx_r[pp][1][tid];
            d2 = sdx_r[pp][2][tid];
            #pragma unroll
            for (int k = 0; k < KBUR; k++) {
                u64 w  = swb_p[pp][k];
                u64 d3 = sdx_r[pp][(k+3)&3][tid + ((k+3)>>2)];
                u0 = f2fma(d0,w,u0); u1 = f2fma(d1,w,u1);
                u2 = f2fma(d2,w,u2); u3 = f2fma(d3,w,u3);
                d0 = d1; d1 = d2; d2 = d3;
            }
            xm[pp][0] = f2fma(sx_r[pp][0][tid+3], c02, f2add(e0,u0));
            xm[pp][1] = f2fma(sx_r[pp][1][tid+3], c02, f2add(e1,u1));
            xm[pp][2] = f2fma(sx_r[pp][2][tid+3], c02, f2add(e2,u2));
            xm[pp][3] = f2fma(sx_r[pp][3][tid+3], c02, f2add(e3,u3));
        }
        #pragma unroll
        for (int r = 0; r < 4; r++) {
            float m0,m1,m2,m3;
            unpack2(xm[0][r], m0, m1); unpack2(xm[1][r], m2, m3);
            u64 dd0 = dup2(m0), dd1 = dup2(m1), dd2 = dup2(m2), dd3 = dup2(m3);
            u64 s01 = 0ull, s23 = 0ull;
            s01 = f2fma(dd0, Wp01[0], s01); s01 = f2fma(dd1, Wp01[1], s01);
            s01 = f2fma(dd2, Wp01[2], s01); s01 = f2fma(dd3, Wp01[3], s01);
            s23 = f2fma(dd0, Wp23[0], s23); s23 = f2fma(dd1, Wp23[1], s23);
            s23 = f2fma(dd2, Wp23[2], s23); s23 = f2fma(dd3, Wp23[3], s23);
            int tb = t0 - 4 + 4*tid + r;
            if (tb < 0 || tb >= T_) { s01 = 0ull; s23 = 0ull; }
            sS0_r[0][r][tid] = s01;
            sS0_r[1][r][tid] = s23;
        }
    }
    __syncthreads();

    // Phase C: dwconv K=9 + gelu, pointwise + gelu, mask, xs, m_time. 4 pts/thread.
    if (tid < 125) {
        const int i0 = 4 * tid;
        u64 aa[2][4];
        #pragma unroll
        for (int pp = 0; pp < 2; pp++) {
            u64 a0=0,a1=0,a2=0,a3=0;
            u64 d0 = sS0_r[pp][0][tid];
            u64 d1 = sS0_r[pp][1][tid];
            u64 d2 = sS0_r[pp][2][tid];
            #pragma unroll
            for (int k = 0; k < KPRE; k++) {
                u64 w  = swd_p[pp][k];
                u64 d3 = sS0_r[pp][(k+3)&3][tid + ((k+3)>>2)];
                a0 = f2fma(d0,w,a0); a1 = f2fma(d1,w,a1);
                a2 = f2fma(d2,w,a2); a3 = f2fma(d3,w,a3);
                d0 = d1; d1 = d2; d2 = d3;
            }
            aa[pp][0]=a0; aa[pp][1]=a1; aa[pp][2]=a2; aa[pp][3]=a3;
        }
        #pragma unroll
        for (int r = 0; r < 4; r++) {
            float g0,g1,g2,g3;
            unpack2(aa[0][r], g0, g1); unpack2(aa[1][r], g2, g3);
            float s1_0 = gelu_fast(g0), s1_1 = gelu_fast(g1);
            float s1_2 = gelu_fast(g2), s1_3 = gelu_fast(g3);

            u64 t01 = 0ull, t23 = 0ull;
            u64 e0 = dup2(s1_0), e1 = dup2(s1_1), e2 = dup2(s1_2), e3 = dup2(s1_3);
            t01 = f2fma(e0, pw01[0], t01); t01 = f2fma(e1, pw01[1], t01);
            t01 = f2fma(e2, pw01[2], t01); t01 = f2fma(e3, pw01[3], t01);
            t23 = f2fma(e0, pw23[0], t23); t23 = f2fma(e1, pw23[1], t23);
            t23 = f2fma(e2, pw23[2], t23); t23 = f2fma(e3, pw23[3], t23);
            float v0,v1,v2,v3;
            unpack2(t01, v0, v1); unpack2(t23, v2, v3);

            unsigned mk = smask_r[r][tid];
            float4 smv = slut[mk];
            float4 xs;
            xs.x = gelu_fast(v0) * smv.x;
            xs.y = gelu_fast(v1) * smv.y;
            xs.z = gelu_fast(v2) * smv.z;
            xs.w = gelu_fast(v3) * smv.w;
            g_xs[(size_t)b * T_ + t0 + i0 + r] = xs;
            smt[i0 + r] = slmt[mk];
        }
    }
    __syncthreads();

    // m_patch: 20 patches per tile
    if (tid < TILE / PATCH) {
        float s = 0.f;
        int base = tid * PATCH;
        #pragma unroll
        for (int p = 0; p < PATCH; p++) s += smt[base + p];
        out_mpatch[b * L_ + tile * (TILE/PATCH) + tid] =
            (s * (1.0f/25.0f) > 0.1f) ? 1.0f : 0.0f;
    }
}

// ---------------------------------------------------------------------------
// Stage 2: reverted to R12 103us version. [128000x100]x[100x160] + LayerNorm.
// ---------------------------------------------------------------------------
__global__ __launch_bounds__(S2T, 1) void stage2_kernel(
    const float* __restrict__ w_proj, const float* __restrict__ ln_gamma,
    const float* __restrict__ ln_beta, float* __restrict__ out_h)
{
    extern __shared__ float sm2[];
    float* sW = sm2;
    float* sA = sm2 + 16000;

    const int tid = threadIdx.x;
    const int tx  = tid & 31;
    const int ty  = tid >> 5;

    for (int i = tid; i < 8000; i += S2T) {
        int kk = i / 160, d = i - kk*160;
        int k0 = 2*kk, k1 = 2*kk + 1;
        float2 w;
        w.x = w_proj[d*100 + (k0 & 3)*25 + (k0 >> 2)];
        w.y = w_proj[d*100 + (k1 & 3)*25 + (k1 >> 2)];
        *(float2*)&sW[2*i] = w;
    }
    float gam[5], bet[5];
    #pragma unroll
    for (int c = 0; c < 5; c++) { gam[c] = ln_gamma[tx + 32*c]; bet[c] = ln_beta[tx + 32*c]; }

    const float4* gxs = (const float4*)g_xs;
    u32 sA_u32;
    { void* p = sA; asm("{ .reg .u64 t; cvta.to.shared.u64 t, %1; cvt.u32.u64 %0, t; }"
                        : "=r"(sA_u32) : "l"(p)); }

    {
        int base = blockIdx.x * (NR2*25);
        #pragma unroll
        for (int it = 0; it < 7; it++) {
            int i = tid + it * S2T;
            if (i < NR2*25) {
                int r = i / 25, p = i - r*25;
                cpasync16(sA_u32 + (r*AROW + 4*p)*4, gxs + base + i);
            }
        }
        CP_COMMIT();
    }

    int cur = 0;
    for (int tt = blockIdx.x; tt < NT2; tt += S2GRID) {
        int nt = tt + S2GRID;
        if (nt < NT2) {
            int base = nt * (NR2*25);
            u32 dst = sA_u32 + (u32)(cur^1) * (S2ABUF*4);
            #pragma unroll
            for (int it = 0; it < 7; it++) {
                int i = tid + it * S2T;
                if (i < NR2*25) {
                    int r = i / 25, p = i - r*25;
                    cpasync16(dst + (r*AROW + 4*p)*4, gxs + base + i);
                }
            }
        }
        CP_COMMIT();
        CP_WAIT1();
        __syncthreads();

        u64 acc[8][5];
        #pragma unroll
        for (int r = 0; r < 8; r++)
            #pragma unroll
            for (int c = 0; c < 5; c++) acc[r][c] = 0ull;

        const float* aT = sA + cur * S2ABUF + (ty*8) * AROW;
        const u64*   wp = (const u64*)sW;

        #pragma unroll 10
        for (int kk = 0; kk < 50; kk++) {
            u64 wv[5];
            #pragma unroll
            for (int c = 0; c < 5; c++) wv[c] = wp[kk*160 + tx + 32*c];
            #pragma unroll
            for (int r = 0; r < 8; r++) {
                u64 av = *(const u64*)(aT + r*AROW + 2*kk);
                #pragma unroll
                for (int c = 0; c < 5; c++) acc[r][c] = f2fma(av, wv[c], acc[r][c]);
            }
        }

        #pragma unroll
        for (int r = 0; r < 8; r++) {
            float h[5]; float s = 0.f, q = 0.f;
            #pragma unroll
            for (int c = 0; c < 5; c++) {
                float lo, hi; unpack2(acc[r][c], lo, hi);
                h[c] = lo + hi;
                s += h[c]; q += h[c]*h[c];
            }
            #pragma unroll
            for (int off = 16; off > 0; off >>= 1) {
                s += __shfl_xor_sync(0xffffffffu, s, off);
                q += __shfl_xor_sync(0xffffffffu, q, off);
            }
            float mu = s * (1.0f/160.0f);
            float rs = rsqrtf(q * (1.0f/160.0f) - mu*mu + 1e-5f);
            int rg = tt*NR2 + ty*8 + r;
            float* o = out_h + (size_t)rg * D_ + tx;
            #pragma unroll
            for (int c = 0; c < 5; c++)
                o[32*c] = (h[c] - mu) * rs * gam[c] + bet[c];
        }
        __syncthreads();
        cur ^= 1;
    }
}

// ---------------------------------------------------------------------------
extern "C" void kernel_launch(void* const* d_in, const int* in_sizes, int n_in,
                              void* d_out, int out_size) {
    const float* X           = (const float*)d_in[0];
    const float* M           = (const float*)d_in[1];
    const float* w_env       = (const float*)d_in[2];
    const float* w_burst     = (const float*)d_in[3];
    const float* synergy_raw = (const float*)d_in[4];
    const float* w_pre_dw    = (const float*)d_in[5];
    const float* w_pre_pw    = (const float*)d_in[6];
    const float* w_proj      = (const float*)d_in[7];
    const float* ln_gamma    = (const float*)d_in[8];
    const float* ln_beta     = (const float*)d_in[9];

    float* out_h  = (float*)d_out;
    float* out_mp = out_h + (size_t)B_ * L_ * D_;

    cudaFuncSetAttribute(stage2_kernel,
                         cudaFuncAttributeMaxDynamicSharedMemorySize,
                         S2_SMEM_BYTES);

    dim3 g1(T_ / TILE, B_);
    stage1_kernel<<<g1, NTHR1>>>((const float4*)X, (const float4*)M,
                                 w_env, w_burst, synergy_raw,
                                 w_pre_dw, w_pre_pw, out_mp);
    stage2_kernel<<<S2GRID, S2T, S2_SMEM_BYTES>>>(w_proj, ln_gamma, ln_beta, out_h);
}

// round 16
// speedup vs baseline: 1.3432x; 1.2348x over previous
#include <cuda_runtime.h>
#include <cuda_bf16.h>
#include <cstdint>
#include <stdint.h>
#include <math.h>

#define B_    64
#define T_    50000
#define D_    160
#define PATCH 25
#define L_    2000
#define KENV  25
#define KBUR  9
#define KPRE  9

#define TILE  500
#define NTHR1 128

#define SXN   137
#define SDXN  133
#define SS0N  129

typedef unsigned long long u64;
typedef unsigned int u32;

__device__ float4 g_xs[(size_t)B_ * T_];

__device__ __forceinline__ u64 f2fma(u64 a, u64 b, u64 c) {
    u64 d; asm("fma.rn.f32x2 %0,%1,%2,%3;" : "=l"(d) : "l"(a), "l"(b), "l"(c)); return d;
}
__device__ __forceinline__ u64 f2add(u64 a, u64 b) {
    u64 d; asm("add.rn.f32x2 %0,%1,%2;" : "=l"(d) : "l"(a), "l"(b)); return d;
}
__device__ __forceinline__ u64 dup2(float x) {
    u64 r; asm("mov.b64 %0,{%1,%1};" : "=l"(r) : "f"(x)); return r;
}
__device__ __forceinline__ u64 pack2(float a, float b) {
    u64 r; asm("mov.b64 %0,{%1,%2};" : "=l"(r) : "f"(a), "f"(b)); return r;
}
__device__ __forceinline__ void unpack2(u64 v, float& lo, float& hi) {
    asm("mov.b64 {%0,%1},%2;" : "=f"(lo), "=f"(hi) : "l"(v));
}
__device__ __forceinline__ float softplusf_(float v) {
    return fmaxf(v, 0.0f) + log1pf(expf(-fabsf(v)));
}
__device__ __forceinline__ float gelu_fast(float x) {
    float z  = x * 0.70710678118654752f;
    float az = fabsf(z);
    float t  = __fdividef(1.0f, fmaf(0.3275911f, az, 1.0f));
    float p  = t * fmaf(t, fmaf(t, fmaf(t, fmaf(t, 1.061405429f, -1.453152027f),
                                        1.421413741f), -0.284496736f), 0.254829592f);
    float e  = __expf(-az * az);
    float erf_az = fmaf(-p, e, 1.0f);
    float erf_z  = copysignf(erf_az, z);
    return 0.5f * x * (1.0f + erf_z);
}

// ---------------------------------------------------------------------------
// Stage 1: unchanged R14 winner (~85us)
// ---------------------------------------------------------------------------
__global__ __launch_bounds__(NTHR1) void stage1_kernel(
    const float4* __restrict__ X, const float4* __restrict__ M,
    const float*  __restrict__ w_env, const float* __restrict__ w_burst,
    const float*  __restrict__ synergy_raw, const float* __restrict__ w_pre_dw,
    const float*  __restrict__ w_pre_pw, float* __restrict__ out_mpatch)
{
    __shared__ u64 sx_r  [2][4][SXN];
    __shared__ u64 sabs_r[2][4][SXN];
    __shared__ u64 sdx_r [2][4][SDXN];
    __shared__ u64 sS0_r [2][4][SS0N];
    __shared__ unsigned smask_r[4][126];
    __shared__ float smt[TILE];
    __shared__ u64 swe_p[2][KENV], swb_p[2][KBUR], swd_p[2][KPRE];
    __shared__ float4 slut[16];
    __shared__ float  slmt[16];
    __shared__ float  ssp[16];

    const int tid  = threadIdx.x;
    const int tile = blockIdx.x;
    const int b    = blockIdx.y;
    const int t0   = tile * TILE;

    if (tid < 16) ssp[tid] = softplusf_(synergy_raw[tid]);
    if (tid < KENV) {
        swe_p[0][tid] = pack2(0.9f*w_env[tid],    0.9f*w_env[25+tid]);
        swe_p[1][tid] = pack2(0.9f*w_env[50+tid], 0.9f*w_env[75+tid]);
    }
    if (tid < KBUR) {
        swb_p[0][tid] = pack2(0.6f*w_burst[tid],    0.6f*w_burst[9+tid]);
        swb_p[1][tid] = pack2(0.6f*w_burst[18+tid], 0.6f*w_burst[27+tid]);
        swd_p[0][tid] = pack2(w_pre_dw[tid],    w_pre_dw[9+tid]);
        swd_p[1][tid] = pack2(w_pre_dw[18+tid], w_pre_dw[27+tid]);
    }
    __syncthreads();

    float Wm[4][4];
    #pragma unroll
    for (int m = 0; m < 4; m++) {
        float r0 = ssp[m*4+0], r1 = ssp[m*4+1], r2 = ssp[m*4+2], r3 = ssp[m*4+3];
        float inv = __fdividef(1.0f, fmaxf(r0+r1+r2+r3, 1e-6f));
        Wm[m][0]=r0*inv; Wm[m][1]=r1*inv; Wm[m][2]=r2*inv; Wm[m][3]=r3*inv;
    }
    u64 Wp01[4], Wp23[4], pw01[4], pw23[4];
    #pragma unroll
    for (int c = 0; c < 4; c++) {
        Wp01[c] = pack2(Wm[0][c], Wm[1][c]);
        Wp23[c] = pack2(Wm[2][c], Wm[3][c]);
        pw01[c] = pack2(w_pre_pw[0*4+c], w_pre_pw[1*4+c]);
        pw23[c] = pack2(w_pre_pw[2*4+c], w_pre_pw[3*4+c]);
    }

    if (tid < 16) {
        float mm[4]; float4 sv;
        #pragma unroll
        for (int c = 0; c < 4; c++) mm[c] = (float)((tid >> c) & 1);
        float v0 = Wm[0][0]*mm[0]+Wm[0][1]*mm[1]+Wm[0][2]*mm[2]+Wm[0][3]*mm[3];
        float v1 = Wm[1][0]*mm[0]+Wm[1][1]*mm[1]+Wm[1][2]*mm[2]+Wm[1][3]*mm[3];
        float v2 = Wm[2][0]*mm[0]+Wm[2][1]*mm[1]+Wm[2][2]*mm[2]+Wm[2][3]*mm[3];
        float v3 = Wm[3][0]*mm[0]+Wm[3][1]*mm[1]+Wm[3][2]*mm[2]+Wm[3][3]*mm[3];
        sv.x = fminf(fmaxf(v0,0.f),1.f); sv.y = fminf(fmaxf(v1,0.f),1.f);
        sv.z = fminf(fmaxf(v2,0.f),1.f); sv.w = fminf(fmaxf(v3,0.f),1.f);
        slut[tid] = sv;
        slmt[tid] = ((sv.x+sv.y+sv.z+sv.w) > 0.f) ? 1.f : 0.f;
    }

    const float4* Xb = X + (size_t)b * T_;
    const float4* Mb = M + (size_t)b * T_;
    for (int j = tid; j < TILE + 32; j += NTHR1) {
        int t = t0 - 16 + j;
        u64 x01 = 0, x23 = 0, a01 = 0, a23 = 0;
        if (t >= 0 && t < T_) {
            float4 X4 = Xb[t], M4 = Mb[t];
            float xx = X4.x*M4.x, xy = X4.y*M4.y, xz = X4.z*M4.z, xw = X4.w*M4.w;
            x01 = pack2(xx, xy); x23 = pack2(xz, xw);
            a01 = pack2(fabsf(xx), fabsf(xy)); a23 = pack2(fabsf(xz), fabsf(xw));
            if (j >= 16 && j < 16 + TILE) {
                unsigned mk = (M4.x > 0.f ? 1u : 0u) | (M4.y > 0.f ? 2u : 0u)
                            | (M4.z > 0.f ? 4u : 0u) | (M4.w > 0.f ? 8u : 0u);
                smask_r[(j-16)&3][(j-16)>>2] = mk;
            }
        }
        int jr = j & 3, jq = j >> 2;
        sx_r[0][jr][jq] = x01;  sx_r[1][jr][jq] = x23;
        sabs_r[0][jr][jq] = a01; sabs_r[1][jr][jq] = a23;
    }
    __syncthreads();

    for (int i = tid; i < TILE + 16; i += NTHR1) {
        int t = t0 - 8 + i;
        u64 r01 = 0, r23 = 0;
        if (t >= 1 && t < T_) {
            int ja = i + 8, jc = i + 7;
            u64 a01 = sx_r[0][ja&3][ja>>2], a23 = sx_r[1][ja&3][ja>>2];
            u64 c01 = sx_r[0][jc&3][jc>>2], c23 = sx_r[1][jc&3][jc>>2];
            float ax, ay, az, aw, cx, cy, cz, cw;
            unpack2(a01, ax, ay); unpack2(a23, az, aw);
            unpack2(c01, cx, cy); unpack2(c23, cz, cw);
            r01 = pack2(fabsf(ax-cx), fabsf(ay-cy));
            r23 = pack2(fabsf(az-cz), fabsf(aw-cw));
        }
        sdx_r[0][i&3][i>>2] = r01; sdx_r[1][i&3][i>>2] = r23;
    }
    __syncthreads();

    const u64 c02 = pack2(0.2f, 0.2f);

    if (tid < 127) {
        u64 xm[2][4];
        #pragma unroll
        for (int pp = 0; pp < 2; pp++) {
            u64 e0=0,e1=0,e2=0,e3=0;
            u64 d0 = sabs_r[pp][0][tid];
            u64 d1 = sabs_r[pp][1][tid];
            u64 d2 = sabs_r[pp][2][tid];
            #pragma unroll
            for (int k = 0; k < KENV; k++) {
                u64 w  = swe_p[pp][k];
                u64 d3 = sabs_r[pp][(k+3)&3][tid + ((k+3)>>2)];
                e0 = f2fma(d0,w,e0); e1 = f2fma(d1,w,e1);
                e2 = f2fma(d2,w,e2); e3 = f2fma(d3,w,e3);
                d0 = d1; d1 = d2; d2 = d3;
            }
            u64 u0=0,u1=0,u2=0,u3=0;
            d0 = sdx_r[pp][0][tid];
            d1 = sdx_r[pp][1][tid];
            d2 = sdx_r[pp][2][tid];
            #pragma unroll
            for (int k = 0; k < KBUR; k++) {
                u64 w  = swb_p[pp][k];
                u64 d3 = sdx_r[pp][(k+3)&3][tid + ((k+3)>>2)];
                u0 = f2fma(d0,w,u0); u1 = f2fma(d1,w,u1);
                u2 = f2fma(d2,w,u2); u3 = f2fma(d3,w,u3);
                d0 = d1; d1 = d2; d2 = d3;
            }
            xm[pp][0] = f2fma(sx_r[pp][0][tid+3], c02, f2add(e0,u0));
            xm[pp][1] = f2fma(sx_r[pp][1][tid+3], c02, f2add(e1,u1));
            xm[pp][2] = f2fma(sx_r[pp][2][tid+3], c02, f2add(e2,u2));
            xm[pp][3] = f2fma(sx_r[pp][3][tid+3], c02, f2add(e3,u3));
        }
        #pragma unroll
        for (int r = 0; r < 4; r++) {
            float m0,m1,m2,m3;
            unpack2(xm[0][r], m0, m1); unpack2(xm[1][r], m2, m3);
            u64 dd0 = dup2(m0), dd1 = dup2(m1), dd2 = dup2(m2), dd3 = dup2(m3);
            u64 s01 = 0ull, s23 = 0ull;
            s01 = f2fma(dd0, Wp01[0], s01); s01 = f2fma(dd1, Wp01[1], s01);
            s01 = f2fma(dd2, Wp01[2], s01); s01 = f2fma(dd3, Wp01[3], s01);
            s23 = f2fma(dd0, Wp23[0], s23); s23 = f2fma(dd1, Wp23[1], s23);
            s23 = f2fma(dd2, Wp23[2], s23); s23 = f2fma(dd3, Wp23[3], s23);
            int tb = t0 - 4 + 4*tid + r;
            if (tb < 0 || tb >= T_) { s01 = 0ull; s23 = 0ull; }
            sS0_r[0][r][tid] = s01;
            sS0_r[1][r][tid] = s23;
        }
    }
    __syncthreads();

    if (tid < 125) {
        const int i0 = 4 * tid;
        u64 aa[2][4];
        #pragma unroll
        for (int pp = 0; pp < 2; pp++) {
            u64 a0=0,a1=0,a2=0,a3=0;
            u64 d0 = sS0_r[pp][0][tid];
            u64 d1 = sS0_r[pp][1][tid];
            u64 d2 = sS0_r[pp][2][tid];
            #pragma unroll
            for (int k = 0; k < KPRE; k++) {
                u64 w  = swd_p[pp][k];
                u64 d3 = sS0_r[pp][(k+3)&3][tid + ((k+3)>>2)];
                a0 = f2fma(d0,w,a0); a1 = f2fma(d1,w,a1);
                a2 = f2fma(d2,w,a2); a3 = f2fma(d3,w,a3);
                d0 = d1; d1 = d2; d2 = d3;
            }
            aa[pp][0]=a0; aa[pp][1]=a1; aa[pp][2]=a2; aa[pp][3]=a3;
        }
        #pragma unroll
        for (int r = 0; r < 4; r++) {
            float g0,g1,g2,g3;
            unpack2(aa[0][r], g0, g1); unpack2(aa[1][r], g2, g3);
            float s1_0 = gelu_fast(g0), s1_1 = gelu_fast(g1);
            float s1_2 = gelu_fast(g2), s1_3 = gelu_fast(g3);

            u64 t01 = 0ull, t23 = 0ull;
            u64 e0 = dup2(s1_0), e1 = dup2(s1_1), e2 = dup2(s1_2), e3 = dup2(s1_3);
            t01 = f2fma(e0, pw01[0], t01); t01 = f2fma(e1, pw01[1], t01);
            t01 = f2fma(e2, pw01[2], t01); t01 = f2fma(e3, pw01[3], t01);
            t23 = f2fma(e0, pw23[0], t23); t23 = f2fma(e1, pw23[1], t23);
            t23 = f2fma(e2, pw23[2], t23); t23 = f2fma(e3, pw23[3], t23);
            float v0,v1,v2,v3;
            unpack2(t01, v0, v1); unpack2(t23, v2, v3);

            unsigned mk = smask_r[r][tid];
            float4 smv = slut[mk];
            float4 xs;
            xs.x = gelu_fast(v0) * smv.x;
            xs.y = gelu_fast(v1) * smv.y;
            xs.z = gelu_fast(v2) * smv.z;
            xs.w = gelu_fast(v3) * smv.w;
            g_xs[(size_t)b * T_ + t0 + i0 + r] = xs;
            smt[i0 + r] = slmt[mk];
        }
    }
    __syncthreads();

    if (tid < TILE / PATCH) {
        float s = 0.f;
        int base = tid * PATCH;
        #pragma unroll
        for (int p = 0; p < PATCH; p++) s += smt[base + p];
        out_mpatch[b * L_ + tile * (TILE/PATCH) + tid] =
            (s * (1.0f/25.0f) > 0.1f) ? 1.0f : 0.0f;
    }
}

// ===========================================================================
// Stage 2 (mma.sync bf16 split precision): C = A_hi*W_hi + A_hi*W_lo + A_lo*W_hi
// A: [128 x 120] bf16 row-major (k-major), stride 240B (conflict-free ldmatrix)
// W: [112 x 168] bf16 k-major rows (W^T), stride 336B (conflict-free .trans)
// Warp tile: 32 rows x 40 cols. 16 warps = 4 rowgroups x 4 colgroups.
// ===========================================================================
#define S3T    512
#define S3GRID 148
#define NT3    1000

#define SM_AHI   0
#define SM_ALO   30720                  // 128*240
#define SM_WHI   61440
#define SM_WLO   99072                  // + 112*336
#define SM_RED   136704                 // [128][4] float2 = 4096
#define SM_STATS 140800                 // [128] float2 = 1024
#define SM_TOT   141824

__device__ __forceinline__ u32 smem_u32(const void* p) {
    u32 a; asm("{ .reg .u64 t; cvta.to.shared.u64 t, %1; cvt.u32.u64 %0, t; }"
               : "=r"(a) : "l"(p));
    return a;
}
__device__ __forceinline__ u32 cvt_bf2(float lo, float hi) {  // low16=bf16(lo)
    u32 r; asm("cvt.rn.satfinite.bf16x2.f32 %0, %1, %2;" : "=r"(r) : "f"(hi), "f"(lo));
    return r;
}
__device__ __forceinline__ float bflo(u32 u) { return __uint_as_float(u << 16); }
__device__ __forceinline__ float bfhi(u32 u) { return __uint_as_float(u & 0xFFFF0000u); }

__device__ __forceinline__ void ldsm_x4(u32* f, u32 addr) {
    asm volatile("ldmatrix.sync.aligned.m8n8.x4.shared.b16 {%0,%1,%2,%3}, [%4];"
                 : "=r"(f[0]), "=r"(f[1]), "=r"(f[2]), "=r"(f[3]) : "r"(addr));
}
__device__ __forceinline__ void ldsm_x2t(u32* f, u32 addr) {
    asm volatile("ldmatrix.sync.aligned.m8n8.x2.trans.shared.b16 {%0,%1}, [%2];"
                 : "=r"(f[0]), "=r"(f[1]) : "r"(addr));
}
__device__ __forceinline__ void mma_bf16(float* c, const u32* a, const u32* b) {
    asm volatile("mma.sync.aligned.m16n8k16.row.col.f32.bf16.bf16.f32 "
                 "{%0,%1,%2,%3}, {%4,%5,%6,%7}, {%8,%9}, {%0,%1,%2,%3};"
                 : "+f"(c[0]), "+f"(c[1]), "+f"(c[2]), "+f"(c[3])
                 : "r"(a[0]), "r"(a[1]), "r"(a[2]), "r"(a[3]), "r"(b[0]), "r"(b[1]));
}

__global__ __launch_bounds__(S3T, 1) void stage2m_kernel(
    const float* __restrict__ w_proj, const float* __restrict__ ln_gamma,
    const float* __restrict__ ln_beta, float* __restrict__ out_h)
{
    extern __shared__ char sm[];
    const u32 smb = smem_u32(sm);
    const int tid = threadIdx.x;
    const int wid = tid >> 5;
    const int lid = tid & 31;
    const int gid = lid >> 2;        // groupID
    const int q   = lid & 3;         // thread-in-group
    const int R   = (wid >> 2) * 32; // row base
    const int N   = (wid & 3) * 40;  // col base

    // zero A/W regions (pads must stay zero)
    for (int i = tid; i < SM_RED / 8; i += S3T) ((u64*)sm)[i] = 0ull;
    __syncthreads();

    // W conversion: sW[k][d] k-major, k = 4p+m <- w_proj[d*100 + m*25 + p]
    for (int i = tid; i < 16000; i += S3T) {
        int d = i / 100, k = i - d * 100;
        int p = k >> 2, m = k & 3;
        float v = w_proj[d * 100 + m * 25 + p];
        __nv_bfloat16 bh = __float2bfloat16_rn(v);
        float lo = v - __bfloat162float(bh);
        __nv_bfloat16 bl = __float2bfloat16_rn(lo);
        *(__nv_bfloat16*)(sm + SM_WHI + k * 336 + d * 2) = bh;
        *(__nv_bfloat16*)(sm + SM_WLO + k * 336 + d * 2) = bl;
    }

    // ln params for this thread's 10 columns
    float2 gamv[5], betv[5];
    #pragma unroll
    for (int nb = 0; nb < 5; nb++) {
        int col = N + nb * 8 + 2 * q;
        gamv[nb] = *(const float2*)&ln_gamma[col];
        betv[nb] = *(const float2*)&ln_beta[col];
    }

    // ldmatrix base addresses
    const u32 aHiB = smb + SM_AHI + (R + (lid & 15)) * 240 + 16 * ((lid >> 4) & 1);
    const u32 aLoB = aHiB + (SM_ALO - SM_AHI);
    u32 bHiB[5];
    #pragma unroll
    for (int nb = 0; nb < 5; nb++)
        bHiB[nb] = smb + SM_WHI + (lid & 15) * 336 + (N + 8 * nb) * 2;

    float2* red   = (float2*)(sm + SM_RED);    // [128][4]
    float2* stats = (float2*)(sm + SM_STATS);  // [128]
    const float4* gxs = (const float4*)g_xs;
    __syncthreads();

    for (int tt = blockIdx.x; tt < NT3; tt += S3GRID) {
        // A conversion: 128 rows x 25 float4
        const float4* gx = gxs + (size_t)tt * 3200;
        #pragma unroll
        for (int it = 0; it < 7; it++) {
            int i = tid + it * S3T;
            if (i < 3200) {
                int r = i / 25, p = i - r * 25;
                float4 v = gx[i];
                u32 h01 = cvt_bf2(v.x, v.y), h23 = cvt_bf2(v.z, v.w);
                float l0 = v.x - bflo(h01), l1 = v.y - bfhi(h01);
                float l2 = v.z - bflo(h23), l3 = v.w - bfhi(h23);
                u32 o01 = cvt_bf2(l0, l1), o23 = cvt_bf2(l2, l3);
                *(u64*)(sm + SM_AHI + r * 240 + 8 * p) = (u64)h01 | ((u64)h23 << 32);
                *(u64*)(sm + SM_ALO + r * 240 + 8 * p) = (u64)o01 | ((u64)o23 << 32);
            }
        }
        __syncthreads();

        // mainloop: warp computes 32 rows x 40 cols
        float acc[2][5][4];
        #pragma unroll
        for (int rb = 0; rb < 2; rb++)
            #pragma unroll
            for (int nb = 0; nb < 5; nb++)
                #pragma unroll
                for (int j = 0; j < 4; j++) acc[rb][nb][j] = 0.f;

        #pragma unroll
        for (int kc = 0; kc < 7; kc++) {
            u32 ah0[4], ah1[4], al0[4], al1[4];
            ldsm_x4(ah0, aHiB + kc * 32);
            ldsm_x4(ah1, aHiB + 3840 + kc * 32);
            ldsm_x4(al0, aLoB + kc * 32);
            ldsm_x4(al1, aLoB + 3840 + kc * 32);
            #pragma unroll
            for (int nb = 0; nb < 5; nb++) {
                u32 bh[2], bl[2];
                ldsm_x2t(bh, bHiB[nb] + kc * 5376);
                ldsm_x2t(bl, bHiB[nb] + (SM_WLO - SM_WHI) + kc * 5376);
                mma_bf16(acc[0][nb], ah0, bh);
                mma_bf16(acc[1][nb], ah1, bh);
                mma_bf16(acc[0][nb], ah0, bl);
                mma_bf16(acc[1][nb], ah1, bl);
                mma_bf16(acc[0][nb], al0, bh);
                mma_bf16(acc[1][nb], al1, bh);
            }
        }

        // epilogue: LayerNorm over 160 per row
        // per-thread partials: rows r0 = R+16rb+gid (c0,c1), r1 = r0+8 (c2,c3)
        #pragma unroll
        for (int rb = 0; rb < 2; rb++) {
            float s0 = 0.f, q0 = 0.f, s1 = 0.f, q1 = 0.f;
            #pragma unroll
            for (int nb = 0; nb < 5; nb++) {
                float c0 = acc[rb][nb][0], c1 = acc[rb][nb][1];
                float c2 = acc[rb][nb][2], c3 = acc[rb][nb][3];
                s0 += c0 + c1; q0 += c0*c0 + c1*c1;
                s1 += c2 + c3; q1 += c2*c2 + c3*c3;
            }
            #pragma unroll
            for (int off = 1; off <= 2; off <<= 1) {
                s0 += __shfl_xor_sync(0xffffffffu, s0, off);
                q0 += __shfl_xor_sync(0xffffffffu, q0, off);
                s1 += __shfl_xor_sync(0xffffffffu, s1, off);
                q1 += __shfl_xor_sync(0xffffffffu, q1, off);
            }
            if (q == 0) {
                int r0 = R + rb * 16 + gid;
                red[r0 * 4 + (wid & 3)]       = make_float2(s0, q0);
                red[(r0 + 8) * 4 + (wid & 3)] = make_float2(s1, q1);
            }
        }
        __syncthreads();
        if (tid < 128) {
            float2 a0 = red[tid*4+0], a1 = red[tid*4+1], a2 = red[tid*4+2], a3 = red[tid*4+3];
            float s = a0.x + a1.x + a2.x + a3.x;
            float qq = a0.y + a1.y + a2.y + a3.y;
            float mu = s * (1.0f / 160.0f);
            float rs = rsqrtf(qq * (1.0f / 160.0f) - mu * mu + 1e-5f);
            stats[tid] = make_float2(mu, rs);
        }
        __syncthreads();

        {
            const size_t rowbase = (size_t)tt * 128;
            #pragma unroll
            for (int rb = 0; rb < 2; rb++) {
                int r0 = R + rb * 16 + gid;
                float2 st0 = stats[r0], st1 = stats[r0 + 8];
                float* o0 = out_h + (rowbase + r0) * D_;
                float* o1 = out_h + (rowbase + r0 + 8) * D_;
                #pragma unroll
                for (int nb = 0; nb < 5; nb++) {
                    int col = N + nb * 8 + 2 * q;
                    float2 h0, h1;
                    h0.x = (acc[rb][nb][0] - st0.x) * st0.y * gamv[nb].x + betv[nb].x;
                    h0.y = (acc[rb][nb][1] - st0.x) * st0.y * gamv[nb].y + betv[nb].y;
                    h1.x = (acc[rb][nb][2] - st1.x) * st1.y * gamv[nb].x + betv[nb].x;
                    h1.y = (acc[rb][nb][3] - st1.x) * st1.y * gamv[nb].y + betv[nb].y;
                    *(float2*)(o0 + col) = h0;
                    *(float2*)(o1 + col) = h1;
                }
            }
        }
        __syncthreads();   // protect sA / red / stats before next tile
    }
}

// ---------------------------------------------------------------------------
extern "C" void kernel_launch(void* const* d_in, const int* in_sizes, int n_in,
                              void* d_out, int out_size) {
    const float* X           = (const float*)d_in[0];
    const float* M           = (const float*)d_in[1];
    const float* w_env       = (const float*)d_in[2];
    const float* w_burst     = (const float*)d_in[3];
    const float* synergy_raw = (const float*)d_in[4];
    const float* w_pre_dw    = (const float*)d_in[5];
    const float* w_pre_pw    = (const float*)d_in[6];
    const float* w_proj      = (const float*)d_in[7];
    const float* ln_gamma    = (const float*)d_in[8];
    const float* ln_beta     = (const float*)d_in[9];

    float* out_h  = (float*)d_out;
    float* out_mp = out_h + (size_t)B_ * L_ * D_;

    cudaFuncSetAttribute(stage2m_kernel,
                         cudaFuncAttributeMaxDynamicSharedMemorySize, SM_TOT);

    dim3 g1(T_ / TILE, B_);
    stage1_kernel<<<g1, NTHR1>>>((const float4*)X, (const float4*)M,
                                 w_env, w_burst, synergy_raw,
                                 w_pre_dw, w_pre_pw, out_mp);
    stage2m_kernel<<<S3GRID, S3T, SM_TOT>>>(w_proj, ln_gamma, ln_beta, out_h);
}